// round 1
// baseline (speedup 1.0000x reference)
#include <cuda_runtime.h>
#include <math.h>

#define S_LEN 2048
#define HIDDEN 2048
#define NH 32
#define NKV 8
#define HD 64
#define KV_W (NKV*HD)   // 512

// Scratch (allocation-free rule: device globals)
__device__ float g_q[S_LEN * HIDDEN];
__device__ float g_k[S_LEN * KV_W];
__device__ float g_v[S_LEN * KV_W];
__device__ float g_attn[S_LEN * HIDDEN];

// ---------------------------------------------------------------------------
// SGEMM (NT): C[M,N] = A[M,K] @ B[N,K]^T   (all row-major, M%128==0, N%128==0,
// K%16==0 guaranteed by problem shapes)
// 128x128x16 tile, 256 threads, 8x8 per thread.
// ---------------------------------------------------------------------------
__global__ __launch_bounds__(256) void sgemm_nt(
    const float* __restrict__ A, const float* __restrict__ B,
    float* __restrict__ C, int M, int N, int K)
{
    const int BM = 128, BN = 128, BK = 16;
    __shared__ float As[BK][BM + 4];
    __shared__ float Bs[BK][BN + 4];

    const int tid = threadIdx.x;
    const int c0 = blockIdx.x * BN;
    const int r0 = blockIdx.y * BM;
    const int tx = tid & 15;
    const int ty = tid >> 4;

    float acc[8][8];
#pragma unroll
    for (int i = 0; i < 8; i++)
#pragma unroll
        for (int j = 0; j < 8; j++) acc[i][j] = 0.f;

    const int lr = tid >> 2;        // 0..63
    const int lk = (tid & 3) * 4;   // 0,4,8,12

    for (int k0 = 0; k0 < K; k0 += BK) {
#pragma unroll
        for (int p = 0; p < 2; p++) {
            int row = lr + p * 64;
            float4 a = *(const float4*)(A + (size_t)(r0 + row) * K + k0 + lk);
            As[lk + 0][row] = a.x; As[lk + 1][row] = a.y;
            As[lk + 2][row] = a.z; As[lk + 3][row] = a.w;
            float4 b = *(const float4*)(B + (size_t)(c0 + row) * K + k0 + lk);
            Bs[lk + 0][row] = b.x; Bs[lk + 1][row] = b.y;
            Bs[lk + 2][row] = b.z; Bs[lk + 3][row] = b.w;
        }
        __syncthreads();

#pragma unroll
        for (int kk = 0; kk < BK; kk++) {
            float a[8], b[8];
            *(float4*)&a[0] = *(const float4*)&As[kk][ty * 8];
            *(float4*)&a[4] = *(const float4*)&As[kk][ty * 8 + 4];
            *(float4*)&b[0] = *(const float4*)&Bs[kk][tx * 8];
            *(float4*)&b[4] = *(const float4*)&Bs[kk][tx * 8 + 4];
#pragma unroll
            for (int i = 0; i < 8; i++)
#pragma unroll
                for (int j = 0; j < 8; j++)
                    acc[i][j] = fmaf(a[i], b[j], acc[i][j]);
        }
        __syncthreads();
    }

#pragma unroll
    for (int i = 0; i < 8; i++) {
        float* crow = C + (size_t)(r0 + ty * 8 + i) * N + c0 + tx * 8;
        float4 s0 = make_float4(acc[i][0], acc[i][1], acc[i][2], acc[i][3]);
        float4 s1 = make_float4(acc[i][4], acc[i][5], acc[i][6], acc[i][7]);
        *(float4*)(crow) = s0;
        *(float4*)(crow + 4) = s1;
    }
}

// ---------------------------------------------------------------------------
// Causal GQA flash attention, fp32.
// grid = (S/64 query tiles, 32 heads), 256 threads.
// Tiles: Q [64x64], K^T (d-major) [64x64], V [64x64], S/P [64x64] in smem.
// Each thread owns a 4x4 output subtile (16x16 thread grid).
// ---------------------------------------------------------------------------
#define FB 68  // padded row length (floats), multiple of 4 for float4 stores

extern __shared__ float fa_sm[];

__global__ __launch_bounds__(256) void flash_attn(
    const float* __restrict__ Q, const float* __restrict__ Kg,
    const float* __restrict__ Vg, float* __restrict__ O)
{
    float* Qs  = fa_sm;                 // [64][FB] row-major (q row, d)
    float* KsT = Qs  + 64 * FB;         // [64][FB] d-major   (d, key)
    float* Vs  = KsT + 64 * FB;         // [64][FB] key-major (key, d)
    float* Ss  = Vs  + 64 * FB;         // [64][FB] (q row, key)
    float* m_sh  = Ss + 64 * FB;        // [64]
    float* l_sh  = m_sh + 64;           // [64]
    float* sc_sh = l_sh + 64;           // [64]

    const int tid = threadIdx.x;
    const int qb = blockIdx.x;
    const int h  = blockIdx.y;
    const int q0 = qb * 64;
    const int kvoff = (h >> 2) * HD;    // GQA: 4 query heads per KV head
    const int tx = tid & 15;
    const int ty = tid >> 4;

    // Load Q tile (64x64 floats)
#pragma unroll
    for (int p = 0; p < 4; p++) {
        int idx = tid + p * 256;
        int r = idx >> 4;
        int f = (idx & 15) * 4;
        float4 v = *(const float4*)(Q + (size_t)(q0 + r) * HIDDEN + h * HD + f);
        *(float4*)&Qs[r * FB + f] = v;
    }
    if (tid < 64) { m_sh[tid] = -1e30f; l_sh[tid] = 0.f; }

    float o[4][4];
#pragma unroll
    for (int i = 0; i < 4; i++)
#pragma unroll
        for (int j = 0; j < 4; j++) o[i][j] = 0.f;

    const int rloc = tid >> 2;   // softmax: row 0..63
    const int qq   = tid & 3;    // softmax: quarter 0..3

    for (int jb = 0; jb <= qb; jb++) {
        const int k0 = jb * 64;
        __syncthreads();  // prior iter's reads of Vs/Ss done; Q stores visible (iter 0)

        // Load K (transposed: d-major) and V tiles
#pragma unroll
        for (int p = 0; p < 4; p++) {
            int idx = tid + p * 256;
            int c = idx >> 4;
            int f = (idx & 15) * 4;
            float4 kv = *(const float4*)(Kg + (size_t)(k0 + c) * KV_W + kvoff + f);
            KsT[(f + 0) * FB + c] = kv.x;
            KsT[(f + 1) * FB + c] = kv.y;
            KsT[(f + 2) * FB + c] = kv.z;
            KsT[(f + 3) * FB + c] = kv.w;
            float4 vv = *(const float4*)(Vg + (size_t)(k0 + c) * KV_W + kvoff + f);
            *(float4*)&Vs[c * FB + f] = vv;
        }
        __syncthreads();

        // GEMM1: S = Q @ K^T
        float acc[4][4];
#pragma unroll
        for (int i = 0; i < 4; i++)
#pragma unroll
            for (int j = 0; j < 4; j++) acc[i][j] = 0.f;

#pragma unroll 8
        for (int kk = 0; kk < 64; kk++) {
            float4 b4 = *(const float4*)&KsT[kk * FB + tx * 4];
            float b[4] = {b4.x, b4.y, b4.z, b4.w};
#pragma unroll
            for (int i = 0; i < 4; i++) {
                float a = Qs[(ty * 4 + i) * FB + kk];
#pragma unroll
                for (int j = 0; j < 4; j++)
                    acc[i][j] = fmaf(a, b[j], acc[i][j]);
            }
        }

        // Scale + causal mask + store to Ss
#pragma unroll
        for (int i = 0; i < 4; i++) {
            int gr = q0 + ty * 4 + i;
            float s[4];
#pragma unroll
            for (int j = 0; j < 4; j++) {
                float sv = acc[i][j] * 0.125f;  // 1/sqrt(64)
                if (k0 + tx * 4 + j > gr) sv = -1e30f;
                s[j] = sv;
            }
            *(float4*)&Ss[(ty * 4 + i) * FB + tx * 4] =
                make_float4(s[0], s[1], s[2], s[3]);
        }
        __syncthreads();

        // Online softmax: 4 threads per row, 16 cols each
        {
            const int cbase = qq * 16;
            float mx = -1e30f;
#pragma unroll
            for (int c = 0; c < 16; c++)
                mx = fmaxf(mx, Ss[rloc * FB + cbase + c]);
            mx = fmaxf(mx, __shfl_xor_sync(0xffffffffu, mx, 1));
            mx = fmaxf(mx, __shfl_xor_sync(0xffffffffu, mx, 2));

            float m_old = m_sh[rloc];
            float m_new = fmaxf(m_old, mx);

            float sum = 0.f;
#pragma unroll
            for (int c = 0; c < 16; c++) {
                float p = __expf(Ss[rloc * FB + cbase + c] - m_new);
                Ss[rloc * FB + cbase + c] = p;
                sum += p;
            }
            sum += __shfl_xor_sync(0xffffffffu, sum, 1);
            sum += __shfl_xor_sync(0xffffffffu, sum, 2);

            if (qq == 0) {
                float sc = __expf(m_old - m_new);
                sc_sh[rloc] = sc;
                l_sh[rloc] = l_sh[rloc] * sc + sum;
                m_sh[rloc] = m_new;
            }
        }
        __syncthreads();

        // Rescale O, then GEMM2: O += P @ V
#pragma unroll
        for (int i = 0; i < 4; i++) {
            float sc = sc_sh[ty * 4 + i];
#pragma unroll
            for (int j = 0; j < 4; j++) o[i][j] *= sc;
        }
#pragma unroll 8
        for (int kk = 0; kk < 64; kk++) {
            float4 b4 = *(const float4*)&Vs[kk * FB + tx * 4];
            float b[4] = {b4.x, b4.y, b4.z, b4.w};
#pragma unroll
            for (int i = 0; i < 4; i++) {
                float a = Ss[(ty * 4 + i) * FB + kk];
#pragma unroll
                for (int j = 0; j < 4; j++)
                    o[i][j] = fmaf(a, b[j], o[i][j]);
            }
        }
    }

    // Normalize + store: attn layout [s][h*64+d]
#pragma unroll
    for (int i = 0; i < 4; i++) {
        float inv = 1.f / l_sh[ty * 4 + i];
        float4 st = make_float4(o[i][0] * inv, o[i][1] * inv,
                                o[i][2] * inv, o[i][3] * inv);
        *(float4*)(O + (size_t)(q0 + ty * 4 + i) * HIDDEN + h * HD + tx * 4) = st;
    }
}

// ---------------------------------------------------------------------------
// kernel_launch
// ---------------------------------------------------------------------------
extern "C" void kernel_launch(void* const* d_in, const int* in_sizes, int n_in,
                              void* d_out, int out_size)
{
    const float* X  = (const float*)d_in[0];
    // d_in[1] = attention_mask (all ones; causal handled in-kernel)
    const float* Wq = (const float*)d_in[2];
    const float* Wk = (const float*)d_in[3];
    const float* Wv = (const float*)d_in[4];
    const float* Wo = (const float*)d_in[5];
    float* out = (float*)d_out;

    float *q, *k, *v, *attn;
    cudaGetSymbolAddress((void**)&q, g_q);
    cudaGetSymbolAddress((void**)&k, g_k);
    cudaGetSymbolAddress((void**)&v, g_v);
    cudaGetSymbolAddress((void**)&attn, g_attn);

    dim3 blk(256);

    // Projections
    sgemm_nt<<<dim3(HIDDEN / 128, S_LEN / 128), blk>>>(X, Wq, q, S_LEN, HIDDEN, HIDDEN);
    sgemm_nt<<<dim3(KV_W / 128, S_LEN / 128), blk>>>(X, Wk, k, S_LEN, KV_W, HIDDEN);
    sgemm_nt<<<dim3(KV_W / 128, S_LEN / 128), blk>>>(X, Wv, v, S_LEN, KV_W, HIDDEN);

    // Flash attention
    const int fa_smem = (4 * 64 * FB + 3 * 64) * (int)sizeof(float);
    cudaFuncSetAttribute(flash_attn, cudaFuncAttributeMaxDynamicSharedMemorySize, fa_smem);
    flash_attn<<<dim3(S_LEN / 64, NH), blk, fa_smem>>>(q, k, v, attn);

    // Output projection
    sgemm_nt<<<dim3(HIDDEN / 128, S_LEN / 128), blk>>>(attn, Wo, out, S_LEN, HIDDEN, HIDDEN);
}

// round 3
// speedup vs baseline: 1.6187x; 1.6187x over previous
#include <cuda_runtime.h>
#include <cuda_bf16.h>
#include <math.h>
#include <stdint.h>

#define S_LEN 2048
#define HIDDEN 2048
#define NH 32
#define NKV 8
#define HD 64
#define KV_W (NKV*HD)   // 512

// ---------------------------------------------------------------------------
// Device-global scratch (allocation-free rule)
// ---------------------------------------------------------------------------
__device__ float g_q[S_LEN * HIDDEN];
__device__ float g_k[S_LEN * KV_W];
__device__ float g_v[S_LEN * KV_W];
__device__ float g_attn[S_LEN * HIDDEN];

__device__ __nv_bfloat16 g_Xh[S_LEN * HIDDEN],   g_Xl[S_LEN * HIDDEN];
__device__ __nv_bfloat16 g_Wqh[HIDDEN * HIDDEN], g_Wql[HIDDEN * HIDDEN];
__device__ __nv_bfloat16 g_Wkh[KV_W * HIDDEN],   g_Wkl[KV_W * HIDDEN];
__device__ __nv_bfloat16 g_Wvh[KV_W * HIDDEN],   g_Wvl[KV_W * HIDDEN];
__device__ __nv_bfloat16 g_Woh[HIDDEN * HIDDEN], g_Wol[HIDDEN * HIDDEN];
__device__ __nv_bfloat16 g_Ath[S_LEN * HIDDEN],  g_Atl[S_LEN * HIDDEN];

// ---------------------------------------------------------------------------
// mma.sync helpers (sm_80+ baseline ISA; works on plain sm_100 target)
// ---------------------------------------------------------------------------
__device__ __forceinline__ uint32_t smem_u32(const void* p) {
    uint32_t a;
    asm("{ .reg .u64 t; cvta.to.shared.u64 t, %1; cvt.u32.u64 %0, t; }"
        : "=r"(a) : "l"(p));
    return a;
}

__device__ __forceinline__ void ldm_x4(uint32_t* r, uint32_t addr) {
    asm volatile("ldmatrix.sync.aligned.m8n8.x4.shared.b16 {%0,%1,%2,%3}, [%4];"
                 : "=r"(r[0]), "=r"(r[1]), "=r"(r[2]), "=r"(r[3]) : "r"(addr));
}
__device__ __forceinline__ void ldm_x2(uint32_t* r, uint32_t addr) {
    asm volatile("ldmatrix.sync.aligned.m8n8.x2.shared.b16 {%0,%1}, [%2];"
                 : "=r"(r[0]), "=r"(r[1]) : "r"(addr));
}
__device__ __forceinline__ void mma_bf16(float* d, const uint32_t* a, const uint32_t* b) {
    asm volatile(
        "mma.sync.aligned.m16n8k16.row.col.f32.bf16.bf16.f32 "
        "{%0,%1,%2,%3}, {%4,%5,%6,%7}, {%8,%9}, {%0,%1,%2,%3};"
        : "+f"(d[0]), "+f"(d[1]), "+f"(d[2]), "+f"(d[3])
        : "r"(a[0]), "r"(a[1]), "r"(a[2]), "r"(a[3]), "r"(b[0]), "r"(b[1]));
}

// ---------------------------------------------------------------------------
// fp32 -> bf16 hi/lo split conversion
// ---------------------------------------------------------------------------
__global__ __launch_bounds__(256) void cvt_split(
    const float* __restrict__ x, __nv_bfloat16* __restrict__ hi,
    __nv_bfloat16* __restrict__ lo, int n)
{
    int i = (blockIdx.x * 256 + threadIdx.x) * 4;
    if (i >= n) return;
    float4 v = *(const float4*)(x + i);
    __nv_bfloat16 h0 = __float2bfloat16(v.x);
    __nv_bfloat16 h1 = __float2bfloat16(v.y);
    __nv_bfloat16 h2 = __float2bfloat16(v.z);
    __nv_bfloat16 h3 = __float2bfloat16(v.w);
    __nv_bfloat16 l0 = __float2bfloat16(v.x - __bfloat162float(h0));
    __nv_bfloat16 l1 = __float2bfloat16(v.y - __bfloat162float(h1));
    __nv_bfloat16 l2 = __float2bfloat16(v.z - __bfloat162float(h2));
    __nv_bfloat16 l3 = __float2bfloat16(v.w - __bfloat162float(h3));
    __nv_bfloat162* hp = (__nv_bfloat162*)(hi + i);
    __nv_bfloat162* lp = (__nv_bfloat162*)(lo + i);
    hp[0] = __halves2bfloat162(h0, h1);
    hp[1] = __halves2bfloat162(h2, h3);
    lp[0] = __halves2bfloat162(l0, l1);
    lp[1] = __halves2bfloat162(l2, l3);
}

// ---------------------------------------------------------------------------
// Split-bf16 GEMM (NT) on mma.sync: C[M,N] = (Ah+Al)[M,K] @ (Bh+Bl)[N,K]^T
// 128x128 CTA tile, BK=64. 8 warps in 2(M) x 4(N); warp tile 64x32.
// Smem rows padded to 72 b16 (144B) -> conflict-free ldmatrix.
// ---------------------------------------------------------------------------
#define SROW 72                    // b16 per smem row
#define TILE_B16 (128 * SROW)      // 9216 b16 = 18432 B per tile
#define GEMM_SMEM (4 * TILE_B16 * 2)  // 73728 B

extern __shared__ char dyn_smem[];

__global__ __launch_bounds__(256, 2) void gemm_bf16x3(
    const __nv_bfloat16* __restrict__ Ah, const __nv_bfloat16* __restrict__ Al,
    const __nv_bfloat16* __restrict__ Bh, const __nv_bfloat16* __restrict__ Bl,
    float* __restrict__ C, int M, int N, int K)
{
    __nv_bfloat16* sm = (__nv_bfloat16*)dyn_smem;
    __nv_bfloat16* sAh = sm;
    __nv_bfloat16* sAl = sm + TILE_B16;
    __nv_bfloat16* sBh = sm + 2 * TILE_B16;
    __nv_bfloat16* sBl = sm + 3 * TILE_B16;
    const uint32_t smb = smem_u32(sm);

    const int tid = threadIdx.x;
    const int wid = tid >> 5;
    const int lane = tid & 31;
    const int wm = wid >> 2;        // 0..1  (M)
    const int wn = wid & 3;         // 0..3  (N)

    const int r0 = blockIdx.y * 128;
    const int c0 = blockIdx.x * 128;

    const __nv_bfloat16* gA[2] = { Ah + (size_t)r0 * K, Al + (size_t)r0 * K };
    const __nv_bfloat16* gB[2] = { Bh + (size_t)c0 * K, Bl + (size_t)c0 * K };

    float acc[4][4][4];
#pragma unroll
    for (int i = 0; i < 4; i++)
#pragma unroll
        for (int j = 0; j < 4; j++)
#pragma unroll
            for (int e = 0; e < 4; e++) acc[i][j][e] = 0.f;

    // ldmatrix base addresses (bytes)
    const uint32_t aBase = smb +
        ((uint32_t)(wm * 64 + (lane & 15)) * SROW + ((lane >> 4) & 1) * 8) * 2;
    const uint32_t bBase = smb + (uint32_t)(2 * TILE_B16) * 2 +
        ((uint32_t)(wn * 32 + (lane & 7)) * SROW + ((lane >> 3) & 1) * 8) * 2;

    const int ldRow = tid >> 3;       // 0..31 (with p: 0..127)
    const int ldC16 = tid & 7;        // 16B chunk within 128B row

    const int nk = K / 64;
    for (int kc = 0; kc < nk; kc++) {
        // ---- global -> smem (4 tiles of 128 x 64 bf16) ----
#pragma unroll
        for (int t = 0; t < 2; t++) {
#pragma unroll
            for (int p = 0; p < 4; p++) {
                int row = ldRow + p * 32;
                uint4 d = *((const uint4*)(gA[t] + (size_t)row * K + kc * 64) + ldC16);
                *(uint4*)(sm + (size_t)t * TILE_B16 + row * SROW + ldC16 * 8) = d;
                uint4 e = *((const uint4*)(gB[t] + (size_t)row * K + kc * 64) + ldC16);
                *(uint4*)(sm + (size_t)(t + 2) * TILE_B16 + row * SROW + ldC16 * 8) = e;
            }
        }
        __syncthreads();

        // ---- compute: 4 k-steps of 16 ----
#pragma unroll
        for (int ks = 0; ks < 4; ks++) {
            uint32_t bH[4][2], bL[4][2];
#pragma unroll
            for (int nt = 0; nt < 4; nt++) {
                uint32_t baddr = bBase + (uint32_t)(nt * 8 * SROW + ks * 16) * 2;
                ldm_x2(bH[nt], baddr);
                ldm_x2(bL[nt], baddr + (uint32_t)TILE_B16 * 2);
            }
#pragma unroll
            for (int mt = 0; mt < 4; mt++) {
                uint32_t aaddr = aBase + (uint32_t)(mt * 16 * SROW + ks * 16) * 2;
                uint32_t aH[4], aL[4];
                ldm_x4(aH, aaddr);
                ldm_x4(aL, aaddr + (uint32_t)TILE_B16 * 2);
#pragma unroll
                for (int nt = 0; nt < 4; nt++) mma_bf16(acc[mt][nt], aH, bH[nt]);
#pragma unroll
                for (int nt = 0; nt < 4; nt++) mma_bf16(acc[mt][nt], aL, bH[nt]);
#pragma unroll
                for (int nt = 0; nt < 4; nt++) mma_bf16(acc[mt][nt], aH, bL[nt]);
            }
        }
        __syncthreads();
    }

    // ---- epilogue: direct stores (c-fragment layout) ----
    const int cr = lane >> 2;          // 0..7
    const int cc = (lane & 3) * 2;     // 0,2,4,6
#pragma unroll
    for (int mt = 0; mt < 4; mt++) {
#pragma unroll
        for (int nt = 0; nt < 4; nt++) {
            float* base = C + (size_t)(r0 + wm * 64 + mt * 16 + cr) * N
                            + c0 + wn * 32 + nt * 8 + cc;
            *(float2*)base = make_float2(acc[mt][nt][0], acc[mt][nt][1]);
            *(float2*)(base + 8 * (size_t)N) = make_float2(acc[mt][nt][2], acc[mt][nt][3]);
        }
    }
}

// ---------------------------------------------------------------------------
// Causal GQA flash attention, fp32 (unchanged)
// ---------------------------------------------------------------------------
#define FB 68

__global__ __launch_bounds__(256) void flash_attn(
    const float* __restrict__ Q, const float* __restrict__ Kg,
    const float* __restrict__ Vg, float* __restrict__ O)
{
    float* fa_sm = (float*)dyn_smem;
    float* Qs  = fa_sm;
    float* KsT = Qs  + 64 * FB;
    float* Vs  = KsT + 64 * FB;
    float* Ss  = Vs  + 64 * FB;
    float* m_sh  = Ss + 64 * FB;
    float* l_sh  = m_sh + 64;
    float* sc_sh = l_sh + 64;

    const int tid = threadIdx.x;
    const int qb = blockIdx.x;
    const int h  = blockIdx.y;
    const int q0 = qb * 64;
    const int kvoff = (h >> 2) * HD;
    const int tx = tid & 15;
    const int ty = tid >> 4;

#pragma unroll
    for (int p = 0; p < 4; p++) {
        int idx = tid + p * 256;
        int r = idx >> 4;
        int f = (idx & 15) * 4;
        float4 v = *(const float4*)(Q + (size_t)(q0 + r) * HIDDEN + h * HD + f);
        *(float4*)&Qs[r * FB + f] = v;
    }
    if (tid < 64) { m_sh[tid] = -1e30f; l_sh[tid] = 0.f; }

    float o[4][4];
#pragma unroll
    for (int i = 0; i < 4; i++)
#pragma unroll
        for (int j = 0; j < 4; j++) o[i][j] = 0.f;

    const int rloc = tid >> 2;
    const int qq   = tid & 3;

    for (int jb = 0; jb <= qb; jb++) {
        const int k0 = jb * 64;
        __syncthreads();

#pragma unroll
        for (int p = 0; p < 4; p++) {
            int idx = tid + p * 256;
            int c = idx >> 4;
            int f = (idx & 15) * 4;
            float4 kv = *(const float4*)(Kg + (size_t)(k0 + c) * KV_W + kvoff + f);
            KsT[(f + 0) * FB + c] = kv.x;
            KsT[(f + 1) * FB + c] = kv.y;
            KsT[(f + 2) * FB + c] = kv.z;
            KsT[(f + 3) * FB + c] = kv.w;
            float4 vv = *(const float4*)(Vg + (size_t)(k0 + c) * KV_W + kvoff + f);
            *(float4*)&Vs[c * FB + f] = vv;
        }
        __syncthreads();

        float acc[4][4];
#pragma unroll
        for (int i = 0; i < 4; i++)
#pragma unroll
            for (int j = 0; j < 4; j++) acc[i][j] = 0.f;

#pragma unroll 8
        for (int kk = 0; kk < 64; kk++) {
            float4 b4 = *(const float4*)&KsT[kk * FB + tx * 4];
            float b[4] = {b4.x, b4.y, b4.z, b4.w};
#pragma unroll
            for (int i = 0; i < 4; i++) {
                float a = Qs[(ty * 4 + i) * FB + kk];
#pragma unroll
                for (int j = 0; j < 4; j++)
                    acc[i][j] = fmaf(a, b[j], acc[i][j]);
            }
        }

#pragma unroll
        for (int i = 0; i < 4; i++) {
            int gr = q0 + ty * 4 + i;
            float s[4];
#pragma unroll
            for (int j = 0; j < 4; j++) {
                float sv = acc[i][j] * 0.125f;
                if (k0 + tx * 4 + j > gr) sv = -1e30f;
                s[j] = sv;
            }
            *(float4*)&Ss[(ty * 4 + i) * FB + tx * 4] =
                make_float4(s[0], s[1], s[2], s[3]);
        }
        __syncthreads();

        {
            const int cbase = qq * 16;
            float mx = -1e30f;
#pragma unroll
            for (int c = 0; c < 16; c++)
                mx = fmaxf(mx, Ss[rloc * FB + cbase + c]);
            mx = fmaxf(mx, __shfl_xor_sync(0xffffffffu, mx, 1));
            mx = fmaxf(mx, __shfl_xor_sync(0xffffffffu, mx, 2));

            float m_old = m_sh[rloc];
            float m_new = fmaxf(m_old, mx);

            float sum = 0.f;
#pragma unroll
            for (int c = 0; c < 16; c++) {
                float p = __expf(Ss[rloc * FB + cbase + c] - m_new);
                Ss[rloc * FB + cbase + c] = p;
                sum += p;
            }
            sum += __shfl_xor_sync(0xffffffffu, sum, 1);
            sum += __shfl_xor_sync(0xffffffffu, sum, 2);

            if (qq == 0) {
                float sc = __expf(m_old - m_new);
                sc_sh[rloc] = sc;
                l_sh[rloc] = l_sh[rloc] * sc + sum;
                m_sh[rloc] = m_new;
            }
        }
        __syncthreads();

#pragma unroll
        for (int i = 0; i < 4; i++) {
            float sc = sc_sh[ty * 4 + i];
#pragma unroll
            for (int j = 0; j < 4; j++) o[i][j] *= sc;
        }
#pragma unroll 8
        for (int kk = 0; kk < 64; kk++) {
            float4 b4 = *(const float4*)&Vs[kk * FB + tx * 4];
            float b[4] = {b4.x, b4.y, b4.z, b4.w};
#pragma unroll
            for (int i = 0; i < 4; i++) {
                float a = Ss[(ty * 4 + i) * FB + kk];
#pragma unroll
                for (int j = 0; j < 4; j++)
                    o[i][j] = fmaf(a, b[j], o[i][j]);
            }
        }
    }

#pragma unroll
    for (int i = 0; i < 4; i++) {
        float inv = 1.f / l_sh[ty * 4 + i];
        float4 st = make_float4(o[i][0] * inv, o[i][1] * inv,
                                o[i][2] * inv, o[i][3] * inv);
        *(float4*)(O + (size_t)(q0 + ty * 4 + i) * HIDDEN + h * HD + tx * 4) = st;
    }
}

// ---------------------------------------------------------------------------
// kernel_launch
// ---------------------------------------------------------------------------
extern "C" void kernel_launch(void* const* d_in, const int* in_sizes, int n_in,
                              void* d_out, int out_size)
{
    const float* X  = (const float*)d_in[0];
    const float* Wq = (const float*)d_in[2];
    const float* Wk = (const float*)d_in[3];
    const float* Wv = (const float*)d_in[4];
    const float* Wo = (const float*)d_in[5];
    float* out = (float*)d_out;

    float *q, *k, *v, *attn;
    cudaGetSymbolAddress((void**)&q, g_q);
    cudaGetSymbolAddress((void**)&k, g_k);
    cudaGetSymbolAddress((void**)&v, g_v);
    cudaGetSymbolAddress((void**)&attn, g_attn);

    __nv_bfloat16 *Xh, *Xl, *Wqh, *Wql, *Wkh, *Wkl, *Wvh, *Wvl, *Woh, *Wol, *Ath, *Atl;
    cudaGetSymbolAddress((void**)&Xh, g_Xh);   cudaGetSymbolAddress((void**)&Xl, g_Xl);
    cudaGetSymbolAddress((void**)&Wqh, g_Wqh); cudaGetSymbolAddress((void**)&Wql, g_Wql);
    cudaGetSymbolAddress((void**)&Wkh, g_Wkh); cudaGetSymbolAddress((void**)&Wkl, g_Wkl);
    cudaGetSymbolAddress((void**)&Wvh, g_Wvh); cudaGetSymbolAddress((void**)&Wvl, g_Wvl);
    cudaGetSymbolAddress((void**)&Woh, g_Woh); cudaGetSymbolAddress((void**)&Wol, g_Wol);
    cudaGetSymbolAddress((void**)&Ath, g_Ath); cudaGetSymbolAddress((void**)&Atl, g_Atl);

    // Conversions
    cvt_split<<<(S_LEN * HIDDEN) / 1024, 256>>>(X, Xh, Xl, S_LEN * HIDDEN);
    cvt_split<<<(HIDDEN * HIDDEN) / 1024, 256>>>(Wq, Wqh, Wql, HIDDEN * HIDDEN);
    cvt_split<<<(KV_W * HIDDEN) / 1024, 256>>>(Wk, Wkh, Wkl, KV_W * HIDDEN);
    cvt_split<<<(KV_W * HIDDEN) / 1024, 256>>>(Wv, Wvh, Wvl, KV_W * HIDDEN);
    cvt_split<<<(HIDDEN * HIDDEN) / 1024, 256>>>(Wo, Woh, Wol, HIDDEN * HIDDEN);

    // Projections (mma.sync split-bf16)
    cudaFuncSetAttribute(gemm_bf16x3, cudaFuncAttributeMaxDynamicSharedMemorySize, GEMM_SMEM);
    gemm_bf16x3<<<dim3(HIDDEN / 128, S_LEN / 128), 256, GEMM_SMEM>>>(
        Xh, Xl, Wqh, Wql, q, S_LEN, HIDDEN, HIDDEN);
    gemm_bf16x3<<<dim3(KV_W / 128, S_LEN / 128), 256, GEMM_SMEM>>>(
        Xh, Xl, Wkh, Wkl, k, S_LEN, KV_W, HIDDEN);
    gemm_bf16x3<<<dim3(KV_W / 128, S_LEN / 128), 256, GEMM_SMEM>>>(
        Xh, Xl, Wvh, Wvl, v, S_LEN, KV_W, HIDDEN);

    // Flash attention (fp32)
    const int fa_smem = (4 * 64 * FB + 3 * 64) * (int)sizeof(float);
    cudaFuncSetAttribute(flash_attn, cudaFuncAttributeMaxDynamicSharedMemorySize, fa_smem);
    flash_attn<<<dim3(S_LEN / 64, NH), 256, fa_smem>>>(q, k, v, attn);

    // Output projection
    cvt_split<<<(S_LEN * HIDDEN) / 1024, 256>>>(attn, Ath, Atl, S_LEN * HIDDEN);
    gemm_bf16x3<<<dim3(HIDDEN / 128, S_LEN / 128), 256, GEMM_SMEM>>>(
        Ath, Atl, Woh, Wol, out, S_LEN, HIDDEN, HIDDEN);
}

// round 4
// speedup vs baseline: 2.6277x; 1.6234x over previous
#include <cuda_runtime.h>
#include <cuda_bf16.h>
#include <math.h>
#include <stdint.h>

#define S_LEN 2048
#define HIDDEN 2048
#define NH 32
#define NKV 8
#define HD 64
#define KV_W (NKV*HD)   // 512

// ---------------------------------------------------------------------------
// Device-global scratch (allocation-free rule)
// ---------------------------------------------------------------------------
__device__ __nv_bfloat16 g_Xh[S_LEN * HIDDEN],   g_Xl[S_LEN * HIDDEN];
__device__ __nv_bfloat16 g_Wqh[HIDDEN * HIDDEN], g_Wql[HIDDEN * HIDDEN];
__device__ __nv_bfloat16 g_Wkh[KV_W * HIDDEN],   g_Wkl[KV_W * HIDDEN];
__device__ __nv_bfloat16 g_Wvh[KV_W * HIDDEN],   g_Wvl[KV_W * HIDDEN];
__device__ __nv_bfloat16 g_Woh[HIDDEN * HIDDEN], g_Wol[HIDDEN * HIDDEN];

__device__ __nv_bfloat16 g_qh[S_LEN * HIDDEN], g_ql[S_LEN * HIDDEN];
__device__ __nv_bfloat16 g_kh[S_LEN * KV_W],   g_kl[S_LEN * KV_W];
__device__ __nv_bfloat16 g_vh[S_LEN * KV_W],   g_vl[S_LEN * KV_W];
__device__ __nv_bfloat16 g_Ath[S_LEN * HIDDEN], g_Atl[S_LEN * HIDDEN];

// ---------------------------------------------------------------------------
// mma.sync helpers (sm_80+ baseline ISA)
// ---------------------------------------------------------------------------
__device__ __forceinline__ uint32_t smem_u32(const void* p) {
    uint32_t a;
    asm("{ .reg .u64 t; cvta.to.shared.u64 t, %1; cvt.u32.u64 %0, t; }"
        : "=r"(a) : "l"(p));
    return a;
}
__device__ __forceinline__ void ldm_x4(uint32_t* r, uint32_t addr) {
    asm volatile("ldmatrix.sync.aligned.m8n8.x4.shared.b16 {%0,%1,%2,%3}, [%4];"
                 : "=r"(r[0]), "=r"(r[1]), "=r"(r[2]), "=r"(r[3]) : "r"(addr));
}
__device__ __forceinline__ void ldm_x2(uint32_t* r, uint32_t addr) {
    asm volatile("ldmatrix.sync.aligned.m8n8.x2.shared.b16 {%0,%1}, [%2];"
                 : "=r"(r[0]), "=r"(r[1]) : "r"(addr));
}
__device__ __forceinline__ void ldm_x2t(uint32_t* r, uint32_t addr) {
    asm volatile("ldmatrix.sync.aligned.m8n8.x2.trans.shared.b16 {%0,%1}, [%2];"
                 : "=r"(r[0]), "=r"(r[1]) : "r"(addr));
}
__device__ __forceinline__ void mma_bf16(float* d, const uint32_t* a, const uint32_t* b) {
    asm volatile(
        "mma.sync.aligned.m16n8k16.row.col.f32.bf16.bf16.f32 "
        "{%0,%1,%2,%3}, {%4,%5,%6,%7}, {%8,%9}, {%0,%1,%2,%3};"
        : "+f"(d[0]), "+f"(d[1]), "+f"(d[2]), "+f"(d[3])
        : "r"(a[0]), "r"(a[1]), "r"(a[2]), "r"(a[3]), "r"(b[0]), "r"(b[1]));
}
__device__ __forceinline__ uint32_t pack_bf2(float lo, float hi) {
    __nv_bfloat162 t = __halves2bfloat162(__float2bfloat16(lo), __float2bfloat16(hi));
    return *reinterpret_cast<uint32_t*>(&t);
}

// ---------------------------------------------------------------------------
// fp32 -> bf16 hi/lo split conversion
// ---------------------------------------------------------------------------
__global__ __launch_bounds__(256) void cvt_split(
    const float* __restrict__ x, __nv_bfloat16* __restrict__ hi,
    __nv_bfloat16* __restrict__ lo, int n)
{
    int i = (blockIdx.x * 256 + threadIdx.x) * 4;
    if (i >= n) return;
    float4 v = *(const float4*)(x + i);
    __nv_bfloat16 h0 = __float2bfloat16(v.x), h1 = __float2bfloat16(v.y);
    __nv_bfloat16 h2 = __float2bfloat16(v.z), h3 = __float2bfloat16(v.w);
    __nv_bfloat16 l0 = __float2bfloat16(v.x - __bfloat162float(h0));
    __nv_bfloat16 l1 = __float2bfloat16(v.y - __bfloat162float(h1));
    __nv_bfloat16 l2 = __float2bfloat16(v.z - __bfloat162float(h2));
    __nv_bfloat16 l3 = __float2bfloat16(v.w - __bfloat162float(h3));
    __nv_bfloat162* hp = (__nv_bfloat162*)(hi + i);
    __nv_bfloat162* lp = (__nv_bfloat162*)(lo + i);
    hp[0] = __halves2bfloat162(h0, h1);
    hp[1] = __halves2bfloat162(h2, h3);
    lp[0] = __halves2bfloat162(l0, l1);
    lp[1] = __halves2bfloat162(l2, l3);
}

// ---------------------------------------------------------------------------
// Split-bf16 GEMM (NT): C = (Ah+Al)[M,K] @ (Bh+Bl)[N,K]^T
// Epilogue: fp32 C (if Cf != nullptr) or bf16 hi/lo pair (Ch/Cl).
// ---------------------------------------------------------------------------
#define SROW 72
#define TILE_B16 (128 * SROW)
#define GEMM_SMEM (4 * TILE_B16 * 2)

extern __shared__ char dyn_smem[];

__global__ __launch_bounds__(256, 2) void gemm_bf16x3(
    const __nv_bfloat16* __restrict__ Ah, const __nv_bfloat16* __restrict__ Al,
    const __nv_bfloat16* __restrict__ Bh, const __nv_bfloat16* __restrict__ Bl,
    float* __restrict__ Cf,
    __nv_bfloat16* __restrict__ Ch, __nv_bfloat16* __restrict__ Cl,
    int M, int N, int K)
{
    __nv_bfloat16* sm = (__nv_bfloat16*)dyn_smem;
    const uint32_t smb = smem_u32(sm);

    const int tid = threadIdx.x;
    const int wid = tid >> 5;
    const int lane = tid & 31;
    const int wm = wid >> 2;
    const int wn = wid & 3;

    const int r0 = blockIdx.y * 128;
    const int c0 = blockIdx.x * 128;

    const __nv_bfloat16* gA[2] = { Ah + (size_t)r0 * K, Al + (size_t)r0 * K };
    const __nv_bfloat16* gB[2] = { Bh + (size_t)c0 * K, Bl + (size_t)c0 * K };

    float acc[4][4][4];
#pragma unroll
    for (int i = 0; i < 4; i++)
#pragma unroll
        for (int j = 0; j < 4; j++)
#pragma unroll
            for (int e = 0; e < 4; e++) acc[i][j][e] = 0.f;

    const uint32_t aBase = smb +
        ((uint32_t)(wm * 64 + (lane & 15)) * SROW + ((lane >> 4) & 1) * 8) * 2;
    const uint32_t bBase = smb + (uint32_t)(2 * TILE_B16) * 2 +
        ((uint32_t)(wn * 32 + (lane & 7)) * SROW + ((lane >> 3) & 1) * 8) * 2;

    const int ldRow = tid >> 3;
    const int ldC16 = tid & 7;

    const int nk = K / 64;
    for (int kc = 0; kc < nk; kc++) {
#pragma unroll
        for (int t = 0; t < 2; t++) {
#pragma unroll
            for (int p = 0; p < 4; p++) {
                int row = ldRow + p * 32;
                uint4 d = *((const uint4*)(gA[t] + (size_t)row * K + kc * 64) + ldC16);
                *(uint4*)(sm + (size_t)t * TILE_B16 + row * SROW + ldC16 * 8) = d;
                uint4 e = *((const uint4*)(gB[t] + (size_t)row * K + kc * 64) + ldC16);
                *(uint4*)(sm + (size_t)(t + 2) * TILE_B16 + row * SROW + ldC16 * 8) = e;
            }
        }
        __syncthreads();

#pragma unroll
        for (int ks = 0; ks < 4; ks++) {
            uint32_t bH[4][2], bL[4][2];
#pragma unroll
            for (int nt = 0; nt < 4; nt++) {
                uint32_t baddr = bBase + (uint32_t)(nt * 8 * SROW + ks * 16) * 2;
                ldm_x2(bH[nt], baddr);
                ldm_x2(bL[nt], baddr + (uint32_t)TILE_B16 * 2);
            }
#pragma unroll
            for (int mt = 0; mt < 4; mt++) {
                uint32_t aaddr = aBase + (uint32_t)(mt * 16 * SROW + ks * 16) * 2;
                uint32_t aH[4], aL[4];
                ldm_x4(aH, aaddr);
                ldm_x4(aL, aaddr + (uint32_t)TILE_B16 * 2);
#pragma unroll
                for (int nt = 0; nt < 4; nt++) mma_bf16(acc[mt][nt], aH, bH[nt]);
#pragma unroll
                for (int nt = 0; nt < 4; nt++) mma_bf16(acc[mt][nt], aL, bH[nt]);
#pragma unroll
                for (int nt = 0; nt < 4; nt++) mma_bf16(acc[mt][nt], aH, bL[nt]);
            }
        }
        __syncthreads();
    }

    const int cr = lane >> 2;
    const int cc = (lane & 3) * 2;
    if (Cf) {
#pragma unroll
        for (int mt = 0; mt < 4; mt++) {
#pragma unroll
            for (int nt = 0; nt < 4; nt++) {
                float* base = Cf + (size_t)(r0 + wm * 64 + mt * 16 + cr) * N
                                 + c0 + wn * 32 + nt * 8 + cc;
                *(float2*)base = make_float2(acc[mt][nt][0], acc[mt][nt][1]);
                *(float2*)(base + 8 * (size_t)N) =
                    make_float2(acc[mt][nt][2], acc[mt][nt][3]);
            }
        }
    } else {
#pragma unroll
        for (int mt = 0; mt < 4; mt++) {
#pragma unroll
            for (int nt = 0; nt < 4; nt++) {
                size_t i0 = (size_t)(r0 + wm * 64 + mt * 16 + cr) * N
                          + c0 + wn * 32 + nt * 8 + cc;
                size_t i1 = i0 + 8 * (size_t)N;
#pragma unroll
                for (int half = 0; half < 2; half++) {
                    size_t ix = half ? i1 : i0;
                    float e0 = acc[mt][nt][half * 2 + 0];
                    float e1 = acc[mt][nt][half * 2 + 1];
                    __nv_bfloat16 h0 = __float2bfloat16(e0);
                    __nv_bfloat16 h1 = __float2bfloat16(e1);
                    float r0f = e0 - __bfloat162float(h0);
                    float r1f = e1 - __bfloat162float(h1);
                    __nv_bfloat162 hp = __halves2bfloat162(h0, h1);
                    __nv_bfloat162 lp = __halves2bfloat162(
                        __float2bfloat16(r0f), __float2bfloat16(r1f));
                    *(uint32_t*)(Ch + ix) = *reinterpret_cast<uint32_t*>(&hp);
                    *(uint32_t*)(Cl + ix) = *reinterpret_cast<uint32_t*>(&lp);
                }
            }
        }
    }
}

// ---------------------------------------------------------------------------
// Flash attention on mma.sync, split-bf16 QK^T and P·V.
// CTA: 128 q-rows x 1 head; 8 warps, each m16 x n64; kv-tiles of 64.
// ---------------------------------------------------------------------------
#define AQH 0
#define AQL 9216
#define AKH 18432
#define AKL 23040
#define AVH 27648
#define AVL 32256
#define FA_SMEM (36864 * 2)

__global__ __launch_bounds__(256) void flash_attn_mma(
    const __nv_bfloat16* __restrict__ Qh_g, const __nv_bfloat16* __restrict__ Ql_g,
    const __nv_bfloat16* __restrict__ Kh_g, const __nv_bfloat16* __restrict__ Kl_g,
    const __nv_bfloat16* __restrict__ Vh_g, const __nv_bfloat16* __restrict__ Vl_g,
    __nv_bfloat16* __restrict__ Oh_g, __nv_bfloat16* __restrict__ Ol_g)
{
    __nv_bfloat16* sm = (__nv_bfloat16*)dyn_smem;
    const uint32_t smb = smem_u32(sm);

    const int tid  = threadIdx.x;
    const int wid  = tid >> 5;
    const int lane = tid & 31;
    const int qb = (int)gridDim.x - 1 - (int)blockIdx.x;  // heavy blocks first
    const int hh = blockIdx.y;
    const int q0 = qb * 128;
    const int kvoff = (hh >> 2) * HD;

    // Load Q hi/lo tiles [128 x 64]
#pragma unroll
    for (int p = 0; p < 8; p++) {
        int idx = tid + p * 256;
        int t = idx >> 10;
        int rem = idx & 1023;
        int r = rem >> 3;
        int c = rem & 7;
        const __nv_bfloat16* src = (t ? Ql_g : Qh_g) +
            (size_t)(q0 + r) * HIDDEN + hh * HD + c * 8;
        uint4 d = *(const uint4*)src;
        *(uint4*)(sm + (t ? AQL : AQH) + r * SROW + c * 8) = d;
    }

    float o[8][4];
#pragma unroll
    for (int nt = 0; nt < 8; nt++)
#pragma unroll
        for (int e = 0; e < 4; e++) o[nt][e] = 0.f;
    float m0 = -1e30f, m1 = -1e30f, l0 = 0.f, l1 = 0.f;

    const int cr = lane >> 2;
    const int cc = (lane & 3) * 2;
    const int row0 = q0 + wid * 16 + cr;
    const int row1 = row0 + 8;

    const uint32_t aHq = smb + (uint32_t)(AQH +
        (wid * 16 + (lane & 15)) * SROW + ((lane >> 4) & 1) * 8) * 2;
    const uint32_t aLq = aHq + (uint32_t)(AQL - AQH) * 2;
    const uint32_t bK = smb + (uint32_t)(AKH +
        (lane & 7) * SROW + ((lane >> 3) & 1) * 8) * 2;
    const uint32_t bV = smb + (uint32_t)(AVH +
        ((lane & 7) + ((lane >> 3) & 1) * 8) * SROW) * 2;

    const int nkv = 2 * qb + 2;
    for (int jb = 0; jb < nkv; jb++) {
        const int k0 = jb * 64;
        __syncthreads();
        // Load K/V hi/lo tiles [64 x 64]
#pragma unroll
        for (int p = 0; p < 8; p++) {
            int idx = tid + p * 256;
            int t = idx >> 9;
            int rem = idx & 511;
            int r = rem >> 3;
            int c = rem & 7;
            const __nv_bfloat16* src =
                (t == 0 ? Kh_g : t == 1 ? Kl_g : t == 2 ? Vh_g : Vl_g) +
                (size_t)(k0 + r) * KV_W + kvoff + c * 8;
            uint4 d = *(const uint4*)src;
            int dst = (t == 0 ? AKH : t == 1 ? AKL : t == 2 ? AVH : AVL);
            *(uint4*)(sm + dst + r * SROW + c * 8) = d;
        }
        __syncthreads();

        // ---- S = Q K^T (3-term split) ----
        float s[8][4];
#pragma unroll
        for (int nt = 0; nt < 8; nt++)
#pragma unroll
            for (int e = 0; e < 4; e++) s[nt][e] = 0.f;

#pragma unroll
        for (int ks = 0; ks < 4; ks++) {
            uint32_t aH[4], aL[4];
            ldm_x4(aH, aHq + ks * 32);
            ldm_x4(aL, aLq + ks * 32);
#pragma unroll
            for (int nt = 0; nt < 8; nt++) {
                uint32_t bh[2], bl[2];
                uint32_t ba = bK + (uint32_t)(nt * 8 * SROW) * 2 + ks * 32;
                ldm_x2(bh, ba);
                ldm_x2(bl, ba + (uint32_t)(AKL - AKH) * 2);
                mma_bf16(s[nt], aH, bh);
                mma_bf16(s[nt], aL, bh);
                mma_bf16(s[nt], aH, bl);
            }
        }

        // ---- scale + causal mask ----
        const bool need_mask = (k0 + 63 > q0);
#pragma unroll
        for (int nt = 0; nt < 8; nt++) {
            int col = k0 + nt * 8 + cc;
            s[nt][0] *= 0.125f; s[nt][1] *= 0.125f;
            s[nt][2] *= 0.125f; s[nt][3] *= 0.125f;
            if (need_mask) {
                if (col > row0)     s[nt][0] = -1e30f;
                if (col + 1 > row0) s[nt][1] = -1e30f;
                if (col > row1)     s[nt][2] = -1e30f;
                if (col + 1 > row1) s[nt][3] = -1e30f;
            }
        }

        // ---- online softmax ----
        float mx0 = -1e30f, mx1 = -1e30f;
#pragma unroll
        for (int nt = 0; nt < 8; nt++) {
            mx0 = fmaxf(mx0, fmaxf(s[nt][0], s[nt][1]));
            mx1 = fmaxf(mx1, fmaxf(s[nt][2], s[nt][3]));
        }
        mx0 = fmaxf(mx0, __shfl_xor_sync(0xffffffffu, mx0, 1));
        mx0 = fmaxf(mx0, __shfl_xor_sync(0xffffffffu, mx0, 2));
        mx1 = fmaxf(mx1, __shfl_xor_sync(0xffffffffu, mx1, 1));
        mx1 = fmaxf(mx1, __shfl_xor_sync(0xffffffffu, mx1, 2));

        float m0n = fmaxf(m0, mx0);
        float m1n = fmaxf(m1, mx1);

        float sum0 = 0.f, sum1 = 0.f;
#pragma unroll
        for (int nt = 0; nt < 8; nt++) {
            s[nt][0] = __expf(s[nt][0] - m0n);
            s[nt][1] = __expf(s[nt][1] - m0n);
            s[nt][2] = __expf(s[nt][2] - m1n);
            s[nt][3] = __expf(s[nt][3] - m1n);
            sum0 += s[nt][0] + s[nt][1];
            sum1 += s[nt][2] + s[nt][3];
        }
        sum0 += __shfl_xor_sync(0xffffffffu, sum0, 1);
        sum0 += __shfl_xor_sync(0xffffffffu, sum0, 2);
        sum1 += __shfl_xor_sync(0xffffffffu, sum1, 1);
        sum1 += __shfl_xor_sync(0xffffffffu, sum1, 2);

        float sc0 = __expf(m0 - m0n);
        float sc1 = __expf(m1 - m1n);
        l0 = l0 * sc0 + sum0;
        l1 = l1 * sc1 + sum1;
        m0 = m0n; m1 = m1n;

#pragma unroll
        for (int nt = 0; nt < 8; nt++) {
            o[nt][0] *= sc0; o[nt][1] *= sc0;
            o[nt][2] *= sc1; o[nt][3] *= sc1;
        }

        // ---- P V (3-term split) ----
#pragma unroll
        for (int ks = 0; ks < 4; ks++) {
            // pack P fragments (hi + residual lo) from c-frags of tiles 2ks, 2ks+1
            uint32_t aP[4], aPl[4];
#pragma unroll
            for (int half = 0; half < 2; half++) {       // half0: k 0-7, half1: k 8-15
                int nt = 2 * ks + half;
#pragma unroll
                for (int rr = 0; rr < 2; rr++) {         // rr0: row cr, rr1: row cr+8
                    float e0 = s[nt][rr * 2 + 0];
                    float e1 = s[nt][rr * 2 + 1];
                    __nv_bfloat16 h0 = __float2bfloat16(e0);
                    __nv_bfloat16 h1 = __float2bfloat16(e1);
                    float r0f = e0 - __bfloat162float(h0);
                    float r1f = e1 - __bfloat162float(h1);
                    __nv_bfloat162 hp = __halves2bfloat162(h0, h1);
                    __nv_bfloat162 lp = __halves2bfloat162(
                        __float2bfloat16(r0f), __float2bfloat16(r1f));
                    aP [half * 2 + rr] = *reinterpret_cast<uint32_t*>(&hp);
                    aPl[half * 2 + rr] = *reinterpret_cast<uint32_t*>(&lp);
                }
            }
#pragma unroll
            for (int nt = 0; nt < 8; nt++) {
                uint32_t bh[2], bl[2];
                uint32_t ba = bV + (uint32_t)(ks * 16 * SROW + nt * 8) * 2;
                ldm_x2t(bh, ba);
                ldm_x2t(bl, ba + (uint32_t)(AVL - AVH) * 2);
                mma_bf16(o[nt], aP,  bh);
                mma_bf16(o[nt], aPl, bh);
                mma_bf16(o[nt], aP,  bl);
            }
        }
    }

    // ---- normalize + store bf16 hi/lo ----
    float inv0 = 1.f / l0;
    float inv1 = 1.f / l1;
#pragma unroll
    for (int nt = 0; nt < 8; nt++) {
        size_t i0 = (size_t)row0 * HIDDEN + hh * HD + nt * 8 + cc;
        size_t i1 = (size_t)row1 * HIDDEN + hh * HD + nt * 8 + cc;
        float e0 = o[nt][0] * inv0, e1 = o[nt][1] * inv0;
        float e2 = o[nt][2] * inv1, e3 = o[nt][3] * inv1;
        __nv_bfloat16 h0 = __float2bfloat16(e0), h1 = __float2bfloat16(e1);
        __nv_bfloat16 h2 = __float2bfloat16(e2), h3 = __float2bfloat16(e3);
        __nv_bfloat162 hp0 = __halves2bfloat162(h0, h1);
        __nv_bfloat162 hp1 = __halves2bfloat162(h2, h3);
        __nv_bfloat162 lp0 = __halves2bfloat162(
            __float2bfloat16(e0 - __bfloat162float(h0)),
            __float2bfloat16(e1 - __bfloat162float(h1)));
        __nv_bfloat162 lp1 = __halves2bfloat162(
            __float2bfloat16(e2 - __bfloat162float(h2)),
            __float2bfloat16(e3 - __bfloat162float(h3)));
        *(uint32_t*)(Oh_g + i0) = *reinterpret_cast<uint32_t*>(&hp0);
        *(uint32_t*)(Oh_g + i1) = *reinterpret_cast<uint32_t*>(&hp1);
        *(uint32_t*)(Ol_g + i0) = *reinterpret_cast<uint32_t*>(&lp0);
        *(uint32_t*)(Ol_g + i1) = *reinterpret_cast<uint32_t*>(&lp1);
    }
}

// ---------------------------------------------------------------------------
// kernel_launch
// ---------------------------------------------------------------------------
extern "C" void kernel_launch(void* const* d_in, const int* in_sizes, int n_in,
                              void* d_out, int out_size)
{
    const float* X  = (const float*)d_in[0];
    const float* Wq = (const float*)d_in[2];
    const float* Wk = (const float*)d_in[3];
    const float* Wv = (const float*)d_in[4];
    const float* Wo = (const float*)d_in[5];
    float* out = (float*)d_out;

    __nv_bfloat16 *Xh, *Xl, *Wqh, *Wql, *Wkh, *Wkl, *Wvh, *Wvl, *Woh, *Wol;
    __nv_bfloat16 *qh, *ql, *kh, *kl, *vh, *vl, *Ath, *Atl;
    cudaGetSymbolAddress((void**)&Xh, g_Xh);   cudaGetSymbolAddress((void**)&Xl, g_Xl);
    cudaGetSymbolAddress((void**)&Wqh, g_Wqh); cudaGetSymbolAddress((void**)&Wql, g_Wql);
    cudaGetSymbolAddress((void**)&Wkh, g_Wkh); cudaGetSymbolAddress((void**)&Wkl, g_Wkl);
    cudaGetSymbolAddress((void**)&Wvh, g_Wvh); cudaGetSymbolAddress((void**)&Wvl, g_Wvl);
    cudaGetSymbolAddress((void**)&Woh, g_Woh); cudaGetSymbolAddress((void**)&Wol, g_Wol);
    cudaGetSymbolAddress((void**)&qh, g_qh);   cudaGetSymbolAddress((void**)&ql, g_ql);
    cudaGetSymbolAddress((void**)&kh, g_kh);   cudaGetSymbolAddress((void**)&kl, g_kl);
    cudaGetSymbolAddress((void**)&vh, g_vh);   cudaGetSymbolAddress((void**)&vl, g_vl);
    cudaGetSymbolAddress((void**)&Ath, g_Ath); cudaGetSymbolAddress((void**)&Atl, g_Atl);

    // Conversions (inputs + weights)
    cvt_split<<<(S_LEN * HIDDEN) / 1024, 256>>>(X, Xh, Xl, S_LEN * HIDDEN);
    cvt_split<<<(HIDDEN * HIDDEN) / 1024, 256>>>(Wq, Wqh, Wql, HIDDEN * HIDDEN);
    cvt_split<<<(KV_W * HIDDEN) / 1024, 256>>>(Wk, Wkh, Wkl, KV_W * HIDDEN);
    cvt_split<<<(KV_W * HIDDEN) / 1024, 256>>>(Wv, Wvh, Wvl, KV_W * HIDDEN);
    cvt_split<<<(HIDDEN * HIDDEN) / 1024, 256>>>(Wo, Woh, Wol, HIDDEN * HIDDEN);

    // QKV projections: bf16 hi/lo outputs (fused split epilogue)
    cudaFuncSetAttribute(gemm_bf16x3, cudaFuncAttributeMaxDynamicSharedMemorySize, GEMM_SMEM);
    gemm_bf16x3<<<dim3(HIDDEN / 128, S_LEN / 128), 256, GEMM_SMEM>>>(
        Xh, Xl, Wqh, Wql, nullptr, qh, ql, S_LEN, HIDDEN, HIDDEN);
    gemm_bf16x3<<<dim3(KV_W / 128, S_LEN / 128), 256, GEMM_SMEM>>>(
        Xh, Xl, Wkh, Wkl, nullptr, kh, kl, S_LEN, KV_W, HIDDEN);
    gemm_bf16x3<<<dim3(KV_W / 128, S_LEN / 128), 256, GEMM_SMEM>>>(
        Xh, Xl, Wvh, Wvl, nullptr, vh, vl, S_LEN, KV_W, HIDDEN);

    // Flash attention (tensor cores)
    cudaFuncSetAttribute(flash_attn_mma, cudaFuncAttributeMaxDynamicSharedMemorySize, FA_SMEM);
    flash_attn_mma<<<dim3(S_LEN / 128, NH), 256, FA_SMEM>>>(
        qh, ql, kh, kl, vh, vl, Ath, Atl);

    // Output projection: fp32 out
    gemm_bf16x3<<<dim3(HIDDEN / 128, S_LEN / 128), 256, GEMM_SMEM>>>(
        Ath, Atl, Woh, Wol, out, nullptr, nullptr, S_LEN, HIDDEN, HIDDEN);
}